// round 8
// baseline (speedup 1.0000x reference)
#include <cuda_runtime.h>
#include <math.h>

// Problem constants
#define N_SAMPLES 32768
#define N_FRAMES  128
#define STEP      (N_SAMPLES / N_FRAMES)   // 256
#define N_FREQS   16
#define POS_DIM   (2 * N_FREQS + 1)        // 33
#define MODEL_DIM 128
#define N_ROWS    512                      // B * N_EVENTS = 32 * 16

#define PI_D 3.14159265358979323846

// ---------------------------------------------------------------------------
// COMPILE-TIME positional-encoding table (unchanged from R7 — passed with
// rel_err 2.38e-7, identical argmaxes to the library-trig version).
// ---------------------------------------------------------------------------
struct PosTable { float v[N_FRAMES * POS_DIM]; };

constexpr double csin_core(double x) {            // |x| <= pi
    double x2 = x * x, term = x, sum = x;
    for (int k = 1; k <= 25; k++) {
        term *= -x2 / (double)((2 * k) * (2 * k + 1));
        sum += term;
    }
    return sum;
}
constexpr double ccos_core(double x) {            // |x| <= pi
    double x2 = x * x, term = 1.0, sum = 1.0;
    for (int k = 1; k <= 25; k++) {
        term *= -x2 / (double)((2 * k - 1) * (2 * k));
        sum += term;
    }
    return sum;
}
constexpr double csqrt_d(double x) {              // Newton, x > 0
    double g = x > 1.0 ? x : 1.0;
    for (int i = 0; i < 80; i++) g = 0.5 * (g + x / g);
    return g;
}

constexpr PosTable make_pos_table() {
    PosTable T{};
    for (int f = 0; f < N_FRAMES; f++) {
        double xd = -PI_D + (double)f * (2.0 * PI_D / 127.0);
        float x = (float)xd;

        double s = csin_core((double)x);
        double c = ccos_core((double)x);

        float feat[POS_DIM] = {};
        feat[0] = x;
        for (int i = 0; i < N_FREQS; i++) {
            feat[1 + 2 * i] = (float)s;           // sin(2^i * x)
            feat[2 + 2 * i] = (float)c;           // cos(2^i * x)
            double s2 = 2.0 * s * c;
            double c2 = 1.0 - 2.0 * s * s;
            s = s2; c = c2;
        }
        float nrm = 0.0f;
        for (int j = 0; j < POS_DIM; j++) nrm += feat[j] * feat[j];
        float inv = 1.0f / ((float)csqrt_d((double)nrm) + 1e-8f);
        for (int j = 0; j < POS_DIM; j++) T.v[f * POS_DIM + j] = feat[j] * inv;
    }
    return T;
}

constexpr PosTable kPosTable = make_pos_table();   // evaluated at compile time
__device__ const PosTable g_pos = kPosTable;

__device__ int g_delay[N_ROWS];

// ---------------------------------------------------------------------------
// Kernel 1: per-row argmax -> delay. Tiny (~2us): 512 blocks x 128 threads.
//   p = time_latent[row] @ W + b (33 vals), sim_f = p . posn_f, block argmax.
//   (p's normalization is a positive per-row scalar: argmax-invariant.)
// ---------------------------------------------------------------------------
__global__ void __launch_bounds__(128) argmax_kernel(
        const float* __restrict__ tl,
        const float* __restrict__ W,
        const float* __restrict__ b) {
    int row = blockIdx.x;
    int tid = threadIdx.x;

    __shared__ float s_tl[MODEL_DIM];
    __shared__ float s_p[POS_DIM];
    __shared__ float s_val[N_FRAMES];
    __shared__ int   s_idx[N_FRAMES];

    s_tl[tid] = tl[row * MODEL_DIM + tid];
    __syncthreads();

    if (tid < POS_DIM) {
        float acc = 0.0f;
#pragma unroll 8
        for (int k = 0; k < MODEL_DIM; k++)
            acc += s_tl[k] * W[k * POS_DIM + tid];   // W is (128, 33) row-major
        s_p[tid] = acc + b[tid];
    }
    __syncthreads();

    float dot = 0.0f;
#pragma unroll
    for (int j = 0; j < POS_DIM; j++)
        dot += s_p[j] * g_pos.v[tid * POS_DIM + j];
    s_val[tid] = dot;
    s_idx[tid] = tid;
    __syncthreads();

    // argmax; exact tie -> lower index (matches jnp.argmax)
    for (int s = 64; s > 0; s >>= 1) {
        if (tid < s) {
            float vu = s_val[tid + s];
            int   iu = s_idx[tid + s];
            if (vu > s_val[tid] || (vu == s_val[tid] && iu < s_idx[tid])) {
                s_val[tid] = vu;
                s_idx[tid] = iu;
            }
        }
        __syncthreads();
    }
    if (tid == 0) g_delay[row] = s_idx[0] * STEP;
}

// ---------------------------------------------------------------------------
// Kernel 2: delta convolution == shift, built for the memory roofline.
//   out[row,t] = (t >= d) ? stems[row, t-d] / 256 : 0
// grid (16, 512) = 8192 blocks x 256 threads -> ~55 blocks/SM over ~7 waves,
// 8 concurrent CTAs = 64 warps/SM (vs 3.5 CTAs in the fused version that
// left the SMs latency-bound at 23% DRAM). Each thread front-batches TWO
// independent float4 loads (MLP_p1=2). d is a multiple of 256 so float4
// accesses stay 16B-aligned on both sides.
// ---------------------------------------------------------------------------
#define CHUNK 2048   // samples per block = 256 threads * 2 float4

__global__ void __launch_bounds__(256) shift_kernel(
        const float* __restrict__ stems,
        float* __restrict__ out) {
    const int row  = blockIdx.y;
    const int tid  = threadIdx.x;
    const int base = blockIdx.x * CHUNK;
    const int d    = g_delay[row];

    const float SCALE = 1.0f / 256.0f;   // 1/sqrt(2*N_SAMPLES), exact pow2

    const float* src = stems + (size_t)row * N_SAMPLES;
    float* dstf      = out   + (size_t)row * N_SAMPLES;

    const int t0 = base + tid * 4;
    const int t1 = t0 + 1024;            // second half of the chunk

    // Front-batch both loads (independent -> 2 LDG.128 in flight per thread)
    float4 a = make_float4(0.f, 0.f, 0.f, 0.f);
    float4 c = make_float4(0.f, 0.f, 0.f, 0.f);
    if (t0 >= d) a = *reinterpret_cast<const float4*>(src + (t0 - d));
    if (t1 >= d) c = *reinterpret_cast<const float4*>(src + (t1 - d));

    a.x *= SCALE; a.y *= SCALE; a.z *= SCALE; a.w *= SCALE;
    c.x *= SCALE; c.y *= SCALE; c.z *= SCALE; c.w *= SCALE;

    *reinterpret_cast<float4*>(dstf + t0) = a;
    *reinterpret_cast<float4*>(dstf + t1) = c;
}

// ---------------------------------------------------------------------------
extern "C" void kernel_launch(void* const* d_in, const int* in_sizes, int n_in,
                              void* d_out, int out_size) {
    // metadata order: time_latent, stems, targets (unused), W, b
    const float* tl    = (const float*)d_in[0];
    const float* stems = (const float*)d_in[1];
    const float* W     = (const float*)d_in[3];
    const float* b     = (const float*)d_in[4];
    float* out = (float*)d_out;

    argmax_kernel<<<N_ROWS, 128>>>(tl, W, b);

    dim3 grid(N_SAMPLES / CHUNK, N_ROWS);   // (16, 512)
    shift_kernel<<<grid, 256>>>(stems, out);
}